// round 1
// baseline (speedup 1.0000x reference)
#include <cuda_runtime.h>
#include <math.h>

// ---------------------------------------------------------------------------
// Problem constants
// ---------------------------------------------------------------------------
#define Bb   4
#define Tt   1024
#define Dd   1024
#define Hh   16
#define DK   64
#define DV   64
#define II   2816
#define EPSf 1e-6f
#define ROWS (Bb*Tt)              // 4096

// ---------------------------------------------------------------------------
// Scratch (static device memory; no allocations allowed)
// ---------------------------------------------------------------------------
__device__ float g_h   [ROWS*Dd];      // rmsnorm(x)
__device__ float g_qpre[ROWS*Dd];
__device__ float g_kpre[ROWS*Dd];
__device__ float g_vpre[ROWS*Dd];
__device__ float g_q   [ROWS*Dd];
__device__ float g_k   [ROWS*Dd];
__device__ float g_v   [ROWS*Dd];
__device__ float g_beta[ROWS*Hh];
__device__ float g_g   [ROWS*Hh];
__device__ float g_o   [ROWS*Dd];      // attn output per head (then o-rmsnormed in place)
__device__ float g_h2  [ROWS*Dd];      // x + attn_out  (residual 2)
__device__ float g_h3  [ROWS*Dd];      // rmsnorm(h2)
__device__ float g_gy  [ROWS*2*II];    // h3 @ Wg
__device__ float g_act [ROWS*II];      // silu(gate)*y

// ---------------------------------------------------------------------------
// RMSNorm over D=1024, one block (256 thr) per row
// ---------------------------------------------------------------------------
__global__ void rmsnorm_kernel(const float* __restrict__ x, const float* __restrict__ w,
                               float* __restrict__ out) {
    int row = blockIdx.x;
    const float4* xr = (const float4*)(x + (size_t)row * Dd);
    float4 v = xr[threadIdx.x];
    float ss = v.x*v.x + v.y*v.y + v.z*v.z + v.w*v.w;
    #pragma unroll
    for (int m = 16; m >= 1; m >>= 1) ss += __shfl_xor_sync(0xffffffffu, ss, m);
    __shared__ float wsum[8];
    if ((threadIdx.x & 31) == 0) wsum[threadIdx.x >> 5] = ss;
    __syncthreads();
    float tot = wsum[0]+wsum[1]+wsum[2]+wsum[3]+wsum[4]+wsum[5]+wsum[6]+wsum[7];
    float r = rsqrtf(tot * (1.0f/Dd) + EPSf);
    float4 wv = ((const float4*)w)[threadIdx.x];
    float4 o;
    o.x = v.x*r*wv.x; o.y = v.y*r*wv.y; o.z = v.z*r*wv.z; o.w = v.w*r*wv.w;
    ((float4*)(out + (size_t)row * Dd))[threadIdx.x] = o;
}

// ---------------------------------------------------------------------------
// SGEMM  C[M,N] = A[M,K] @ B[K,N] (+ addsrc), all row-major, dims divisible by tiles
// BM=128 BN=128 BK=16, 256 threads, 8x8 per thread
// ---------------------------------------------------------------------------
#define BM 128
#define BN 128
#define BK 16
__global__ __launch_bounds__(256) void sgemm_kernel(
    const float* __restrict__ A, const float* __restrict__ B,
    const float* __restrict__ addsrc, float* __restrict__ C,
    int M, int N, int Kd) {
    __shared__ float As[BK][BM];
    __shared__ float Bs[BK][BN];
    int tid = threadIdx.x;
    int tx = tid & 15, ty = tid >> 4;
    int bm = blockIdx.y * BM, bn = blockIdx.x * BN;

    float acc[8][8];
    #pragma unroll
    for (int i = 0; i < 8; i++)
        #pragma unroll
        for (int j = 0; j < 8; j++) acc[i][j] = 0.0f;

    int arow  = tid >> 2;          // 0..63
    int acol4 = (tid & 3) * 4;     // 0,4,8,12
    int brow  = tid >> 5;          // 0..7
    int bcol4 = (tid & 31) * 4;    // 0..124

    for (int k0 = 0; k0 < Kd; k0 += BK) {
        #pragma unroll
        for (int r = 0; r < 2; r++) {
            int row = arow + r * 64;
            float4 va = *(const float4*)(A + (size_t)(bm + row) * Kd + k0 + acol4);
            As[acol4+0][row] = va.x;
            As[acol4+1][row] = va.y;
            As[acol4+2][row] = va.z;
            As[acol4+3][row] = va.w;
        }
        #pragma unroll
        for (int r = 0; r < 2; r++) {
            int row = brow + r * 8;
            *(float4*)(&Bs[row][bcol4]) =
                *(const float4*)(B + (size_t)(k0 + row) * N + bn + bcol4);
        }
        __syncthreads();
        #pragma unroll
        for (int kk = 0; kk < BK; kk++) {
            float a[8], b[8];
            #pragma unroll
            for (int i = 0; i < 8; i++) a[i] = As[kk][ty*8 + i];
            #pragma unroll
            for (int j = 0; j < 8; j++) b[j] = Bs[kk][tx*8 + j];
            #pragma unroll
            for (int i = 0; i < 8; i++)
                #pragma unroll
                for (int j = 0; j < 8; j++)
                    acc[i][j] += a[i] * b[j];
        }
        __syncthreads();
    }

    #pragma unroll
    for (int i = 0; i < 8; i++) {
        int row = bm + ty*8 + i;
        #pragma unroll
        for (int j = 0; j < 8; j += 4) {
            int col = bn + tx*8 + j;
            float4 v = make_float4(acc[i][j], acc[i][j+1], acc[i][j+2], acc[i][j+3]);
            if (addsrc) {
                float4 s = *(const float4*)(addsrc + (size_t)row * N + col);
                v.x += s.x; v.y += s.y; v.z += s.z; v.w += s.w;
            }
            *(float4*)(C + (size_t)row * N + col) = v;
        }
    }
}

// ---------------------------------------------------------------------------
// Causal depthwise conv1d (K=4) + SiLU.  x: [B,T,1024], w: [1024,4]
// ---------------------------------------------------------------------------
__global__ void conv_silu_kernel(const float* __restrict__ xin, const float* __restrict__ w,
                                 float* __restrict__ out) {
    int idx = blockIdx.x * blockDim.x + threadIdx.x;   // over B*T*1024
    int c = idx & 1023;
    int bt = idx >> 10;
    int t = bt & (Tt - 1);
    float4 w4 = ((const float4*)w)[c];                 // w[c][0..3]
    float acc = xin[idx] * w4.w;
    if (t >= 1) acc += xin[idx - 1024] * w4.z;
    if (t >= 2) acc += xin[idx - 2048] * w4.y;
    if (t >= 3) acc += xin[idx - 3072] * w4.x;
    out[idx] = acc / (1.0f + expf(-acc));              // silu
}

// ---------------------------------------------------------------------------
// Per-(b,t,h) L2 norm over 64 elems (+ optional scale).  In place. Warp/group.
// ---------------------------------------------------------------------------
__global__ void l2norm_kernel(float* __restrict__ qk, float scale) {
    int gidx = blockIdx.x * 8 + (threadIdx.x >> 5);    // group over B*T*H = 65536
    int lane = threadIdx.x & 31;
    size_t base = (size_t)(gidx >> 4) * 1024 + (gidx & 15) * 64;
    float a = qk[base + lane], b = qk[base + 32 + lane];
    float ss = a*a + b*b;
    #pragma unroll
    for (int m = 16; m >= 1; m >>= 1) ss += __shfl_xor_sync(0xffffffffu, ss, m);
    float r = rsqrtf(ss + EPSf) * scale;
    qk[base + lane]      = a * r;
    qk[base + 32 + lane] = b * r;
}

// ---------------------------------------------------------------------------
// Per-(b,t,h) RMSNorm over DV=64 with weight. In place.
// ---------------------------------------------------------------------------
__global__ void o_rmsnorm_kernel(float* __restrict__ o, const float* __restrict__ w) {
    int gidx = blockIdx.x * 8 + (threadIdx.x >> 5);
    int lane = threadIdx.x & 31;
    size_t base = (size_t)gidx * 64;
    float a = o[base + lane], b = o[base + 32 + lane];
    float ss = a*a + b*b;
    #pragma unroll
    for (int m = 16; m >= 1; m >>= 1) ss += __shfl_xor_sync(0xffffffffu, ss, m);
    float r = rsqrtf(ss * (1.0f/64.0f) + EPSf);
    o[base + lane]      = a * r * w[lane];
    o[base + 32 + lane] = b * r * w[lane + 32];
}

// ---------------------------------------------------------------------------
// beta / g projections: per row computes h@Wb, h@Wa -> beta, g. One block/row.
// ---------------------------------------------------------------------------
__global__ void betag_kernel(const float* __restrict__ h,
                             const float* __restrict__ Wb, const float* __restrict__ Wa,
                             const float* __restrict__ dt_bias, const float* __restrict__ A_log,
                             float* __restrict__ beta, float* __restrict__ g) {
    int row = blockIdx.x;
    __shared__ float hs[Dd];
    ((float4*)hs)[threadIdx.x] = ((const float4*)(h + (size_t)row * Dd))[threadIdx.x];
    __syncthreads();
    int hh = threadIdx.x >> 4;   // 0..15
    int l  = threadIdx.x & 15;
    float sb = 0.0f, sa = 0.0f;
    #pragma unroll 8
    for (int j = 0; j < 64; j++) {
        int d = l + 16*j;
        float hv = hs[d];
        sb += hv * Wb[d*Hh + hh];
        sa += hv * Wa[d*Hh + hh];
    }
    #pragma unroll
    for (int m = 8; m >= 1; m >>= 1) {
        sb += __shfl_xor_sync(0xffffffffu, sb, m);
        sa += __shfl_xor_sync(0xffffffffu, sa, m);
    }
    if (l == 0) {
        beta[row*Hh + hh] = 2.0f / (1.0f + expf(-sb));
        float xg = sa + dt_bias[hh];
        float sp = (xg > 15.0f) ? xg : log1pf(expf(xg));
        g[row*Hh + hh] = -expf(A_log[hh]) * sp;
    }
}

// ---------------------------------------------------------------------------
// Gated delta-rule scan. One block per (b,h). 256 threads.
// thread -> (column c = tid>>2, row-group sub = tid&3 owning rows sub*16..+15)
// ---------------------------------------------------------------------------
__global__ __launch_bounds__(256) void scan_kernel(
    const float* __restrict__ q, const float* __restrict__ k, const float* __restrict__ v,
    const float* __restrict__ beta, const float* __restrict__ g,
    float* __restrict__ o, float* __restrict__ state_out) {
    int h = blockIdx.x, b = blockIdx.y;
    int tid = threadIdx.x;
    int c   = tid >> 2;
    int sub = tid & 3;

    __shared__ __align__(16) float sh[2][196];   // [k 0..63 | q 64..127 | v 128..191 | beta 192 | g 193]

    float S[16];
    #pragma unroll
    for (int r = 0; r < 16; r++) S[r] = 0.0f;

    for (int t = 0; t < Tt; t++) {
        float* buf = sh[t & 1];
        size_t off = ((size_t)(b*Tt + t)) * 1024 + h * 64;
        if (tid < 64)        buf[tid]       = k[off + tid];
        else if (tid < 128)  buf[tid]       = q[off + tid - 64];
        else if (tid < 192)  buf[tid]       = v[off + tid - 128];
        else if (tid == 192) buf[192]       = beta[(size_t)(b*Tt + t)*Hh + h];
        else if (tid == 193) buf[193]       = g[(size_t)(b*Tt + t)*Hh + h];
        __syncthreads();

        float eg = expf(buf[193]);
        float bt = buf[192];

        const float4* kp4 = (const float4*)(buf + sub*16);
        const float4* qp4 = (const float4*)(buf + 64 + sub*16);
        float kr[16], qr[16];
        #pragma unroll
        for (int rr = 0; rr < 4; rr++) {
            float4 kv4 = kp4[rr];
            kr[rr*4+0] = kv4.x; kr[rr*4+1] = kv4.y; kr[rr*4+2] = kv4.z; kr[rr*4+3] = kv4.w;
            float4 qv4 = qp4[rr];
            qr[rr*4+0] = qv4.x; qr[rr*4+1] = qv4.y; qr[rr*4+2] = qv4.z; qr[rr*4+3] = qv4.w;
        }

        float kvp = 0.0f;
        #pragma unroll
        for (int r = 0; r < 16; r++) {
            S[r] *= eg;
            kvp += kr[r] * S[r];
        }
        kvp += __shfl_xor_sync(0xffffffffu, kvp, 1);
        kvp += __shfl_xor_sync(0xffffffffu, kvp, 2);

        float delta = (buf[128 + c] - kvp) * bt;

        float op = 0.0f;
        #pragma unroll
        for (int r = 0; r < 16; r++) {
            S[r] += kr[r] * delta;
            op += qr[r] * S[r];
        }
        op += __shfl_xor_sync(0xffffffffu, op, 1);
        op += __shfl_xor_sync(0xffffffffu, op, 2);
        if (sub == 0)
            o[((size_t)(b*Tt + t)*Hh + h) * DV + c] = op;
    }

    // write final state [B,H,DK,DV]
    #pragma unroll
    for (int r = 0; r < 16; r++)
        state_out[((size_t)(b*Hh + h)*DK + sub*16 + r) * DV + c] = S[r];
}

// ---------------------------------------------------------------------------
// SwiGLU: act = silu(gy[:, :I]) * gy[:, I:]
// ---------------------------------------------------------------------------
__global__ void swiglu_kernel(const float* __restrict__ gy, float* __restrict__ act) {
    int idx = blockIdx.x * blockDim.x + threadIdx.x;   // over ROWS*II
    int row = idx / II;
    int i   = idx - row * II;
    float gate = gy[(size_t)row * (2*II) + i];
    float y    = gy[(size_t)row * (2*II) + II + i];
    act[idx] = gate / (1.0f + expf(-gate)) * y;
}

// ---------------------------------------------------------------------------
// launch
// ---------------------------------------------------------------------------
extern "C" void kernel_launch(void* const* d_in, const int* in_sizes, int n_in,
                              void* d_out, int out_size) {
    const float* x           = (const float*)d_in[0];
    const float* attn_norm_w = (const float*)d_in[1];
    const float* Wq          = (const float*)d_in[2];
    const float* Wk          = (const float*)d_in[3];
    const float* Wv          = (const float*)d_in[4];
    const float* cq          = (const float*)d_in[5];
    const float* ck          = (const float*)d_in[6];
    const float* cv          = (const float*)d_in[7];
    const float* Wb          = (const float*)d_in[8];
    const float* Wa          = (const float*)d_in[9];
    const float* dt_bias     = (const float*)d_in[10];
    const float* A_log       = (const float*)d_in[11];
    const float* o_norm_w    = (const float*)d_in[12];
    const float* Wo          = (const float*)d_in[13];
    const float* mlp_norm_w  = (const float*)d_in[14];
    const float* Wg          = (const float*)d_in[15];
    const float* Wd          = (const float*)d_in[16];
    float* out = (float*)d_out;

    float *h, *qpre, *kpre, *vpre, *q, *k, *v, *beta, *gg, *o, *h2, *h3, *gy, *act;
    cudaGetSymbolAddress((void**)&h,    g_h);
    cudaGetSymbolAddress((void**)&qpre, g_qpre);
    cudaGetSymbolAddress((void**)&kpre, g_kpre);
    cudaGetSymbolAddress((void**)&vpre, g_vpre);
    cudaGetSymbolAddress((void**)&q,    g_q);
    cudaGetSymbolAddress((void**)&k,    g_k);
    cudaGetSymbolAddress((void**)&v,    g_v);
    cudaGetSymbolAddress((void**)&beta, g_beta);
    cudaGetSymbolAddress((void**)&gg,   g_g);
    cudaGetSymbolAddress((void**)&o,    g_o);
    cudaGetSymbolAddress((void**)&h2,   g_h2);
    cudaGetSymbolAddress((void**)&h3,   g_h3);
    cudaGetSymbolAddress((void**)&gy,   g_gy);
    cudaGetSymbolAddress((void**)&act,  g_act);

    // 1. h = rmsnorm(x)
    rmsnorm_kernel<<<ROWS, 256>>>(x, attn_norm_w, h);

    // 2. q/k/v projections
    dim3 g1024(Dd/BN, ROWS/BM);
    sgemm_kernel<<<g1024, 256>>>(h, Wq, nullptr, qpre, ROWS, Dd, Dd);
    sgemm_kernel<<<g1024, 256>>>(h, Wk, nullptr, kpre, ROWS, Dd, Dd);
    sgemm_kernel<<<g1024, 256>>>(h, Wv, nullptr, vpre, ROWS, Dd, Dd);

    // 3. conv + silu
    conv_silu_kernel<<<(ROWS*Dd)/256, 256>>>(qpre, cq, q);
    conv_silu_kernel<<<(ROWS*Dd)/256, 256>>>(kpre, ck, k);
    conv_silu_kernel<<<(ROWS*Dd)/256, 256>>>(vpre, cv, v);

    // 4. l2norm (q scaled by DK^-0.5 = 0.125)
    l2norm_kernel<<<(ROWS*Hh)/8, 256>>>(q, 0.125f);
    l2norm_kernel<<<(ROWS*Hh)/8, 256>>>(k, 1.0f);

    // 5. beta / g
    betag_kernel<<<ROWS, 256>>>(h, Wb, Wa, dt_bias, A_log, beta, gg);

    // 6. sequential delta-rule scan; writes o and final state (second output)
    scan_kernel<<<dim3(Hh, Bb), 256>>>(q, k, v, beta, gg, o, out + (size_t)ROWS*Dd);

    // 7. per-head output RMSNorm
    o_rmsnorm_kernel<<<(ROWS*Hh)/8, 256>>>(o, o_norm_w);

    // 8. attn projection + residual: h2 = x + o @ Wo
    sgemm_kernel<<<g1024, 256>>>(o, Wo, x, h2, ROWS, Dd, Dd);

    // 9. MLP
    rmsnorm_kernel<<<ROWS, 256>>>(h2, mlp_norm_w, h3);
    dim3 gwg((2*II)/BN, ROWS/BM);
    sgemm_kernel<<<gwg, 256>>>(h3, Wg, nullptr, gy, ROWS, 2*II, Dd);
    swiglu_kernel<<<(ROWS*II)/256, 256>>>(gy, act);
    sgemm_kernel<<<g1024, 256>>>(act, Wd, h2, out, ROWS, Dd, II);
}

// round 4
// speedup vs baseline: 1.9540x; 1.9540x over previous
#include <cuda_runtime.h>
#include <math.h>

// ---------------------------------------------------------------------------
// Problem constants
// ---------------------------------------------------------------------------
#define Bb   4
#define Tt   1024
#define Dd   1024
#define Hh   16
#define DK   64
#define DV   64
#define II   2816
#define EPSf 1e-6f
#define ROWS (Bb*Tt)              // 4096

// ---------------------------------------------------------------------------
// Scratch (static device memory; no allocations allowed)
// ---------------------------------------------------------------------------
__device__ float g_h   [ROWS*Dd];      // rmsnorm(x)
__device__ float g_qpre[ROWS*Dd];
__device__ float g_kpre[ROWS*Dd];
__device__ float g_vpre[ROWS*Dd];
__device__ float g_q   [ROWS*Dd];
__device__ float g_k   [ROWS*Dd];
__device__ float g_v   [ROWS*Dd];
__device__ float g_beta[ROWS*Hh];
__device__ float g_g   [ROWS*Hh];
__device__ float g_o   [ROWS*Dd];      // attn output per head
__device__ float g_h2  [ROWS*Dd];      // x + attn_out
__device__ float g_h3  [ROWS*Dd];      // rmsnorm(h2)
__device__ float g_gy  [ROWS*2*II];    // h3 @ Wg
__device__ float g_act [ROWS*II];      // silu(gate)*y

// ---------------------------------------------------------------------------
// RMSNorm over D=1024, one block (256 thr) per row
// ---------------------------------------------------------------------------
__global__ void rmsnorm_kernel(const float* __restrict__ x, const float* __restrict__ w,
                               float* __restrict__ out) {
    int row = blockIdx.x;
    const float4* xr = (const float4*)(x + (size_t)row * Dd);
    float4 v = xr[threadIdx.x];
    float ss = v.x*v.x + v.y*v.y + v.z*v.z + v.w*v.w;
    #pragma unroll
    for (int m = 16; m >= 1; m >>= 1) ss += __shfl_xor_sync(0xffffffffu, ss, m);
    __shared__ float wsum[8];
    if ((threadIdx.x & 31) == 0) wsum[threadIdx.x >> 5] = ss;
    __syncthreads();
    float tot = wsum[0]+wsum[1]+wsum[2]+wsum[3]+wsum[4]+wsum[5]+wsum[6]+wsum[7];
    float r = rsqrtf(tot * (1.0f/Dd) + EPSf);
    float4 wv = ((const float4*)w)[threadIdx.x];
    float4 o;
    o.x = v.x*r*wv.x; o.y = v.y*r*wv.y; o.z = v.z*r*wv.z; o.w = v.w*r*wv.w;
    ((float4*)(out + (size_t)row * Dd))[threadIdx.x] = o;
}

// ---------------------------------------------------------------------------
// TF32 tensor-core GEMM body: C[M,N] = A[M,K] @ B[K,N] (+addsrc)
// BM=128 BN=128 BK=32, 256 threads (8 warps, 2x4), warp tile 64x32,
// mma.sync.m16n8k8.tf32, double-buffered dynamic smem, tf32 cvt at STS time.
// ---------------------------------------------------------------------------
#define GBM 128
#define GBN 128
#define GBK 32
#define ASTRIDE 36                 // 32 + 4 pad (floats)
#define BSTRIDE 136                // 128 + 8 pad (floats)
#define AS_STAGE (GBM*ASTRIDE)     // 4608 floats
#define BS_STAGE (GBK*BSTRIDE)     // 4352 floats
#define GEMM_SMEM_BYTES ((2*(AS_STAGE+BS_STAGE))*4)   // 71680 B

__device__ __forceinline__ unsigned f2tf32(float f) {
    unsigned r;
    asm("cvt.rna.tf32.f32 %0, %1;" : "=r"(r) : "f"(f));
    return r;
}

__device__ __forceinline__ void mma_tf32(float& c0, float& c1, float& c2, float& c3,
                                         unsigned a0, unsigned a1, unsigned a2, unsigned a3,
                                         unsigned b0, unsigned b1) {
    asm volatile(
        "mma.sync.aligned.m16n8k8.row.col.f32.tf32.tf32.f32 "
        "{%0,%1,%2,%3}, {%4,%5,%6,%7}, {%8,%9}, {%0,%1,%2,%3};"
        : "+f"(c0), "+f"(c1), "+f"(c2), "+f"(c3)
        : "r"(a0), "r"(a1), "r"(a2), "r"(a3), "r"(b0), "r"(b1));
}

__device__ __forceinline__ void mma_gemm_body(
    const float* __restrict__ A, const float* __restrict__ B,
    const float* __restrict__ addsrc, float* __restrict__ C,
    int N, int Kd, int bm, int bn) {
    extern __shared__ float smem[];
    float* As = smem;                          // 2 stages
    float* Bsm = smem + 2*AS_STAGE;

    int tid = threadIdx.x;
    int lane = tid & 31;
    int w    = tid >> 5;
    int lq = lane >> 2;         // 0..7
    int lr = lane & 3;          // 0..3
    int wm = w >> 2;            // 0..1 -> M offset wm*64
    int wn = w & 3;             // 0..3 -> N offset wn*32

    // staging mapping
    int arow  = tid >> 1;             // 0..127
    int acolh = (tid & 1) * 16;       // 0 or 16
    int brow  = tid >> 3;             // 0..31
    int bcolh = (tid & 7) * 16;       // 0..112

    const float* Ag = A + (size_t)(bm + arow) * Kd + acolh;
    const float* Bg = B + (size_t)brow * N + bn + bcolh;

    float acc[4][4][4];
    #pragma unroll
    for (int mi = 0; mi < 4; mi++)
        #pragma unroll
        for (int ni = 0; ni < 4; ni++)
            #pragma unroll
            for (int r = 0; r < 4; r++) acc[mi][ni][r] = 0.0f;

    int nch = Kd / GBK;

    float4 ar[4], br[4];
    #pragma unroll
    for (int i = 0; i < 4; i++) ar[i] = *(const float4*)(Ag + 4*i);
    #pragma unroll
    for (int i = 0; i < 4; i++) br[i] = *(const float4*)(Bg + 4*i);

    {
        float* as = As;
        float* bs = Bsm;
        #pragma unroll
        for (int i = 0; i < 4; i++) {
            as[arow*ASTRIDE + acolh + 4*i + 0] = __uint_as_float(f2tf32(ar[i].x));
            as[arow*ASTRIDE + acolh + 4*i + 1] = __uint_as_float(f2tf32(ar[i].y));
            as[arow*ASTRIDE + acolh + 4*i + 2] = __uint_as_float(f2tf32(ar[i].z));
            as[arow*ASTRIDE + acolh + 4*i + 3] = __uint_as_float(f2tf32(ar[i].w));
            bs[brow*BSTRIDE + bcolh + 4*i + 0] = __uint_as_float(f2tf32(br[i].x));
            bs[brow*BSTRIDE + bcolh + 4*i + 1] = __uint_as_float(f2tf32(br[i].y));
            bs[brow*BSTRIDE + bcolh + 4*i + 2] = __uint_as_float(f2tf32(br[i].z));
            bs[brow*BSTRIDE + bcolh + 4*i + 3] = __uint_as_float(f2tf32(br[i].w));
        }
    }
    __syncthreads();

    for (int ch = 0; ch < nch; ch++) {
        int s = ch & 1;
        if (ch + 1 < nch) {
            const float* Agn = Ag + (ch + 1) * GBK;
            const float* Bgn = Bg + (size_t)(ch + 1) * GBK * N;
            #pragma unroll
            for (int i = 0; i < 4; i++) ar[i] = *(const float4*)(Agn + 4*i);
            #pragma unroll
            for (int i = 0; i < 4; i++) br[i] = *(const float4*)(Bgn + 4*i);
        }

        const float* as = As + s*AS_STAGE + (wm*64)*ASTRIDE;
        const float* bs = Bsm + s*BS_STAGE + wn*32;

        #pragma unroll
        for (int ks = 0; ks < 4; ks++) {
            int kc = ks * 8;
            unsigned af[4][4];
            #pragma unroll
            for (int mi = 0; mi < 4; mi++) {
                int r0 = mi*16 + lq;
                af[mi][0] = __float_as_uint(as[(r0    )*ASTRIDE + kc + lr    ]);
                af[mi][1] = __float_as_uint(as[(r0 + 8)*ASTRIDE + kc + lr    ]);
                af[mi][2] = __float_as_uint(as[(r0    )*ASTRIDE + kc + lr + 4]);
                af[mi][3] = __float_as_uint(as[(r0 + 8)*ASTRIDE + kc + lr + 4]);
            }
            unsigned bf[4][2];
            #pragma unroll
            for (int ni = 0; ni < 4; ni++) {
                bf[ni][0] = __float_as_uint(bs[(kc + lr    )*BSTRIDE + ni*8 + lq]);
                bf[ni][1] = __float_as_uint(bs[(kc + lr + 4)*BSTRIDE + ni*8 + lq]);
            }
            #pragma unroll
            for (int mi = 0; mi < 4; mi++)
                #pragma unroll
                for (int ni = 0; ni < 4; ni++)
                    mma_tf32(acc[mi][ni][0], acc[mi][ni][1], acc[mi][ni][2], acc[mi][ni][3],
                             af[mi][0], af[mi][1], af[mi][2], af[mi][3],
                             bf[ni][0], bf[ni][1]);
        }

        if (ch + 1 < nch) {
            float* asn = As + (s^1)*AS_STAGE;
            float* bsn = Bsm + (s^1)*BS_STAGE;
            #pragma unroll
            for (int i = 0; i < 4; i++) {
                asn[arow*ASTRIDE + acolh + 4*i + 0] = __uint_as_float(f2tf32(ar[i].x));
                asn[arow*ASTRIDE + acolh + 4*i + 1] = __uint_as_float(f2tf32(ar[i].y));
                asn[arow*ASTRIDE + acolh + 4*i + 2] = __uint_as_float(f2tf32(ar[i].z));
                asn[arow*ASTRIDE + acolh + 4*i + 3] = __uint_as_float(f2tf32(ar[i].w));
                bsn[brow*BSTRIDE + bcolh + 4*i + 0] = __uint_as_float(f2tf32(br[i].x));
                bsn[brow*BSTRIDE + bcolh + 4*i + 1] = __uint_as_float(f2tf32(br[i].y));
                bsn[brow*BSTRIDE + bcolh + 4*i + 2] = __uint_as_float(f2tf32(br[i].z));
                bsn[brow*BSTRIDE + bcolh + 4*i + 3] = __uint_as_float(f2tf32(br[i].w));
            }
            __syncthreads();
        }
    }

    #pragma unroll
    for (int mi = 0; mi < 4; mi++) {
        int r0 = bm + wm*64 + mi*16 + lq;
        #pragma unroll
        for (int ni = 0; ni < 4; ni++) {
            int col = bn + wn*32 + ni*8 + 2*lr;
            float2 v0 = make_float2(acc[mi][ni][0], acc[mi][ni][1]);
            float2 v1 = make_float2(acc[mi][ni][2], acc[mi][ni][3]);
            if (addsrc) {
                float2 s0 = *(const float2*)(addsrc + (size_t)r0 * N + col);
                float2 s1 = *(const float2*)(addsrc + (size_t)(r0+8) * N + col);
                v0.x += s0.x; v0.y += s0.y; v1.x += s1.x; v1.y += s1.y;
            }
            *(float2*)(C + (size_t)r0 * N + col) = v0;
            *(float2*)(C + (size_t)(r0+8) * N + col) = v1;
        }
    }
}

__global__ __launch_bounds__(256, 1) void mma_gemm_kernel(
    const float* __restrict__ A, const float* __restrict__ B,
    const float* __restrict__ addsrc, float* __restrict__ C,
    int N, int Kd) {
    mma_gemm_body(A, B, addsrc, C, N, Kd, blockIdx.y * GBM, blockIdx.x * GBN);
}

// batched QKV: blockIdx.z selects weight/output
__global__ __launch_bounds__(256, 1) void mma_gemm_qkv_kernel(
    const float* __restrict__ A,
    const float* __restrict__ B0, const float* __restrict__ B1, const float* __restrict__ B2,
    float* __restrict__ C0, float* __restrict__ C1, float* __restrict__ C2,
    int N, int Kd) {
    const float* B = (blockIdx.z == 0) ? B0 : ((blockIdx.z == 1) ? B1 : B2);
    float*       C = (blockIdx.z == 0) ? C0 : ((blockIdx.z == 1) ? C1 : C2);
    mma_gemm_body(A, B, nullptr, C, N, Kd, blockIdx.y * GBM, blockIdx.x * GBN);
}

// ---------------------------------------------------------------------------
// Fused causal depthwise conv1d (K=4) + SiLU + optional per-head L2 norm.
// One block per (b,t) row of 1024 channels; 256 threads, 4 channels each.
// Head = 64 channels = 16 threads; reduce within 16-lane groups.
// ---------------------------------------------------------------------------
__global__ void conv_fused_kernel(const float* __restrict__ xin, const float* __restrict__ w,
                                  float* __restrict__ out, float scale, int do_l2) {
    int row = blockIdx.x;            // b*T + t
    int t = row & (Tt - 1);
    int c4 = threadIdx.x * 4;
    size_t base = (size_t)row * Dd + c4;

    float4 x0 = *(const float4*)(xin + base);
    float4 x1 = (t >= 1) ? *(const float4*)(xin + base - Dd)   : make_float4(0,0,0,0);
    float4 x2 = (t >= 2) ? *(const float4*)(xin + base - 2*Dd) : make_float4(0,0,0,0);
    float4 x3 = (t >= 3) ? *(const float4*)(xin + base - 3*Dd) : make_float4(0,0,0,0);

    float y[4];
    #pragma unroll
    for (int j = 0; j < 4; j++) {
        float4 w4 = ((const float4*)w)[c4 + j];     // taps [0..3] for channel
        float xc0 = (&x0.x)[j], xc1 = (&x1.x)[j], xc2 = (&x2.x)[j], xc3 = (&x3.x)[j];
        float a = xc0*w4.w + xc1*w4.z + xc2*w4.y + xc3*w4.x;
        y[j] = a / (1.0f + expf(-a));               // silu
    }

    if (do_l2) {
        float ss = y[0]*y[0] + y[1]*y[1] + y[2]*y[2] + y[3]*y[3];
        // 16 threads per head; xor offsets 1,2,4,8 stay inside the 16-lane group
        #pragma unroll
        for (int m = 8; m >= 1; m >>= 1) ss += __shfl_xor_sync(0xffffffffu, ss, m);
        float r = rsqrtf(ss + EPSf) * scale;
        #pragma unroll
        for (int j = 0; j < 4; j++) y[j] *= r;
    }
    *(float4*)(out + base) = make_float4(y[0], y[1], y[2], y[3]);
}

// ---------------------------------------------------------------------------
// Per-(b,t,h) RMSNorm over DV=64 with weight. In place.
// ---------------------------------------------------------------------------
__global__ void o_rmsnorm_kernel(float* __restrict__ o, const float* __restrict__ w) {
    int gidx = blockIdx.x * 8 + (threadIdx.x >> 5);
    int lane = threadIdx.x & 31;
    size_t base = (size_t)gidx * 64;
    float a = o[base + lane], b = o[base + 32 + lane];
    float ss = a*a + b*b;
    #pragma unroll
    for (int m = 16; m >= 1; m >>= 1) ss += __shfl_xor_sync(0xffffffffu, ss, m);
    float r = rsqrtf(ss * (1.0f/64.0f) + EPSf);
    o[base + lane]      = a * r * w[lane];
    o[base + 32 + lane] = b * r * w[lane + 32];
}

// ---------------------------------------------------------------------------
// beta / g projections
// ---------------------------------------------------------------------------
__global__ void betag_kernel(const float* __restrict__ h,
                             const float* __restrict__ Wb, const float* __restrict__ Wa,
                             const float* __restrict__ dt_bias, const float* __restrict__ A_log,
                             float* __restrict__ beta, float* __restrict__ g) {
    int row = blockIdx.x;
    __shared__ float hs[Dd];
    ((float4*)hs)[threadIdx.x] = ((const float4*)(h + (size_t)row * Dd))[threadIdx.x];
    __syncthreads();
    int hh = threadIdx.x >> 4;
    int l  = threadIdx.x & 15;
    float sb = 0.0f, sa = 0.0f;
    #pragma unroll 8
    for (int j = 0; j < 64; j++) {
        int d = l + 16*j;
        float hv = hs[d];
        sb += hv * Wb[d*Hh + hh];
        sa += hv * Wa[d*Hh + hh];
    }
    #pragma unroll
    for (int m = 8; m >= 1; m >>= 1) {
        sb += __shfl_xor_sync(0xffffffffu, sb, m);
        sa += __shfl_xor_sync(0xffffffffu, sa, m);
    }
    if (l == 0) {
        beta[row*Hh + hh] = 2.0f / (1.0f + expf(-sb));
        float xg = sa + dt_bias[hh];
        float sp = (xg > 15.0f) ? xg : log1pf(expf(xg));
        g[row*Hh + hh] = -expf(A_log[hh]) * sp;
    }
}

// ---------------------------------------------------------------------------
// Gated delta-rule scan with register prefetch. One block per (b,h).
// ---------------------------------------------------------------------------
__device__ __forceinline__ float scan_load(const float* __restrict__ q,
                                           const float* __restrict__ k,
                                           const float* __restrict__ v,
                                           const float* __restrict__ beta,
                                           const float* __restrict__ g,
                                           int b, int h, int t, int tid) {
    size_t off = ((size_t)(b*Tt + t)) * 1024 + h * 64;
    if (tid < 64)  return k[off + tid];
    if (tid < 128) return q[off + tid - 64];
    if (tid < 192) return v[off + tid - 128];
    if (tid == 192) return beta[(size_t)(b*Tt + t)*Hh + h];
    return g[(size_t)(b*Tt + t)*Hh + h];
}

__global__ __launch_bounds__(256) void scan_kernel(
    const float* __restrict__ q, const float* __restrict__ k, const float* __restrict__ v,
    const float* __restrict__ beta, const float* __restrict__ g,
    float* __restrict__ o, float* __restrict__ state_out) {
    int h = blockIdx.x, b = blockIdx.y;
    int tid = threadIdx.x;
    int c   = tid >> 2;
    int sub = tid & 3;

    __shared__ __align__(16) float sh[2][200];

    float S[16];
    #pragma unroll
    for (int r = 0; r < 16; r++) S[r] = 0.0f;

    float rv = (tid < 194) ? scan_load(q, k, v, beta, g, b, h, 0, tid) : 0.0f;

    for (int t = 0; t < Tt; t++) {
        float* buf = sh[t & 1];
        if (tid < 194) buf[tid] = rv;
        __syncthreads();
        if (t + 1 < Tt && tid < 194)
            rv = scan_load(q, k, v, beta, g, b, h, t + 1, tid);

        float eg = expf(buf[193]);
        float bt = buf[192];

        const float4* kp4 = (const float4*)(buf + sub*16);
        const float4* qp4 = (const float4*)(buf + 64 + sub*16);
        float kr[16], qr[16];
        #pragma unroll
        for (int rr = 0; rr < 4; rr++) {
            float4 kv4 = kp4[rr];
            kr[rr*4+0] = kv4.x; kr[rr*4+1] = kv4.y; kr[rr*4+2] = kv4.z; kr[rr*4+3] = kv4.w;
            float4 qv4 = qp4[rr];
            qr[rr*4+0] = qv4.x; qr[rr*4+1] = qv4.y; qr[rr*4+2] = qv4.z; qr[rr*4+3] = qv4.w;
        }

        float kvp = 0.0f;
        #pragma unroll
        for (int r = 0; r < 16; r++) {
            S[r] *= eg;
            kvp += kr[r] * S[r];
        }
        kvp += __shfl_xor_sync(0xffffffffu, kvp, 1);
        kvp += __shfl_xor_sync(0xffffffffu, kvp, 2);

        float delta = (buf[128 + c] - kvp) * bt;

        float op = 0.0f;
        #pragma unroll
        for (int r = 0; r < 16; r++) {
            S[r] += kr[r] * delta;
            op += qr[r] * S[r];
        }
        op += __shfl_xor_sync(0xffffffffu, op, 1);
        op += __shfl_xor_sync(0xffffffffu, op, 2);
        if (sub == 0)
            o[((size_t)(b*Tt + t)*Hh + h) * DV + c] = op;
    }

    #pragma unroll
    for (int r = 0; r < 16; r++)
        state_out[((size_t)(b*Hh + h)*DK + sub*16 + r) * DV + c] = S[r];
}

// ---------------------------------------------------------------------------
// SwiGLU: act = silu(gy[:, :I]) * gy[:, I:]
// ---------------------------------------------------------------------------
__global__ void swiglu_kernel(const float* __restrict__ gy, float* __restrict__ act) {
    int idx = blockIdx.x * blockDim.x + threadIdx.x;
    int row = idx / II;
    int i   = idx - row * II;
    float gate = gy[(size_t)row * (2*II) + i];
    float y    = gy[(size_t)row * (2*II) + II + i];
    act[idx] = gate / (1.0f + expf(-gate)) * y;
}

// ---------------------------------------------------------------------------
// launch
// ---------------------------------------------------------------------------
extern "C" void kernel_launch(void* const* d_in, const int* in_sizes, int n_in,
                              void* d_out, int out_size) {
    const float* x           = (const float*)d_in[0];
    const float* attn_norm_w = (const float*)d_in[1];
    const float* Wq          = (const float*)d_in[2];
    const float* Wk          = (const float*)d_in[3];
    const float* Wv          = (const float*)d_in[4];
    const float* cq          = (const float*)d_in[5];
    const float* ck          = (const float*)d_in[6];
    const float* cv          = (const float*)d_in[7];
    const float* Wb          = (const float*)d_in[8];
    const float* Wa          = (const float*)d_in[9];
    const float* dt_bias     = (const float*)d_in[10];
    const float* A_log       = (const float*)d_in[11];
    const float* o_norm_w    = (const float*)d_in[12];
    const float* Wo          = (const float*)d_in[13];
    const float* mlp_norm_w  = (const float*)d_in[14];
    const float* Wg          = (const float*)d_in[15];
    const float* Wd          = (const float*)d_in[16];
    float* out = (float*)d_out;

    float *h, *qpre, *kpre, *vpre, *q, *k, *v, *beta, *gg, *o, *h2, *h3, *gy, *act;
    cudaGetSymbolAddress((void**)&h,    g_h);
    cudaGetSymbolAddress((void**)&qpre, g_qpre);
    cudaGetSymbolAddress((void**)&kpre, g_kpre);
    cudaGetSymbolAddress((void**)&vpre, g_vpre);
    cudaGetSymbolAddress((void**)&q,    g_q);
    cudaGetSymbolAddress((void**)&k,    g_k);
    cudaGetSymbolAddress((void**)&v,    g_v);
    cudaGetSymbolAddress((void**)&beta, g_beta);
    cudaGetSymbolAddress((void**)&gg,   g_g);
    cudaGetSymbolAddress((void**)&o,    g_o);
    cudaGetSymbolAddress((void**)&h2,   g_h2);
    cudaGetSymbolAddress((void**)&h3,   g_h3);
    cudaGetSymbolAddress((void**)&gy,   g_gy);
    cudaGetSymbolAddress((void**)&act,  g_act);

    cudaFuncSetAttribute(mma_gemm_kernel,
                         cudaFuncAttributeMaxDynamicSharedMemorySize, GEMM_SMEM_BYTES);
    cudaFuncSetAttribute(mma_gemm_qkv_kernel,
                         cudaFuncAttributeMaxDynamicSharedMemorySize, GEMM_SMEM_BYTES);

    // 1. h = rmsnorm(x)
    rmsnorm_kernel<<<ROWS, 256>>>(x, attn_norm_w, h);

    // 2. q/k/v projections — one batched launch (blockIdx.z selects weight)
    dim3 gqkv(Dd/GBN, ROWS/GBM, 3);
    mma_gemm_qkv_kernel<<<gqkv, 256, GEMM_SMEM_BYTES>>>(h, Wq, Wk, Wv,
                                                        qpre, kpre, vpre, Dd, Dd);

    // 3. conv + silu (+ fused l2norm for q,k; q also scaled by DK^-0.5)
    conv_fused_kernel<<<ROWS, 256>>>(qpre, cq, q, 0.125f, 1);
    conv_fused_kernel<<<ROWS, 256>>>(kpre, ck, k, 1.0f,   1);
    conv_fused_kernel<<<ROWS, 256>>>(vpre, cv, v, 1.0f,   0);

    // 4. beta / g
    betag_kernel<<<ROWS, 256>>>(h, Wb, Wa, dt_bias, A_log, beta, gg);

    // 5. delta-rule scan (writes o and final state)
    scan_kernel<<<dim3(Hh, Bb), 256>>>(q, k, v, beta, gg, o, out + (size_t)ROWS*Dd);

    // 6. per-head output RMSNorm
    o_rmsnorm_kernel<<<(ROWS*Hh)/8, 256>>>(o, o_norm_w);

    // 7. attn projection + residual
    dim3 g1024(Dd/GBN, ROWS/GBM);
    mma_gemm_kernel<<<g1024, 256, GEMM_SMEM_BYTES>>>(o, Wo, x, h2, Dd, Dd);

    // 8. MLP
    rmsnorm_kernel<<<ROWS, 256>>>(h2, mlp_norm_w, h3);
    dim3 gwg((2*II)/GBN, ROWS/GBM);
    mma_gemm_kernel<<<gwg, 256, GEMM_SMEM_BYTES>>>(h3, Wg, nullptr, gy, 2*II, Dd);
    swiglu_kernel<<<(ROWS*II)/256, 256>>>(gy, act);
    mma_gemm_kernel<<<g1024, 256, GEMM_SMEM_BYTES>>>(act, Wd, h2, out, Dd, II);
}

// round 5
// speedup vs baseline: 2.2910x; 1.1725x over previous
#include <cuda_runtime.h>
#include <math.h>

// ---------------------------------------------------------------------------
// Problem constants
// ---------------------------------------------------------------------------
#define Bb   4
#define Tt   1024
#define Dd   1024
#define Hh   16
#define DK   64
#define DV   64
#define II   2816
#define EPSf 1e-6f
#define ROWS (Bb*Tt)              // 4096

// ---------------------------------------------------------------------------
// Scratch (static device memory; no allocations allowed)
// ---------------------------------------------------------------------------
__device__ float g_h   [ROWS*Dd];      // rmsnorm(x)
__device__ float g_qpre[ROWS*Dd];
__device__ float g_kpre[ROWS*Dd];
__device__ float g_vpre[ROWS*Dd];
__device__ float g_q   [ROWS*Dd];
__device__ float g_k   [ROWS*Dd];
__device__ float g_v   [ROWS*Dd];
__device__ float g_beta[ROWS*Hh];
__device__ float g_g   [ROWS*Hh];
__device__ float g_o   [ROWS*Dd];      // attn output per head
__device__ float g_h2  [ROWS*Dd];      // x + attn_out
__device__ float g_h3  [ROWS*Dd];      // rmsnorm(h2)
__device__ float g_gy  [ROWS*2*II];    // h3 @ Wg
__device__ float g_act [ROWS*II];      // silu(gate)*y

// ---------------------------------------------------------------------------
// RMSNorm over D=1024, one block (256 thr) per row
// ---------------------------------------------------------------------------
__global__ void rmsnorm_kernel(const float* __restrict__ x, const float* __restrict__ w,
                               float* __restrict__ out) {
    int row = blockIdx.x;
    const float4* xr = (const float4*)(x + (size_t)row * Dd);
    float4 v = xr[threadIdx.x];
    float ss = v.x*v.x + v.y*v.y + v.z*v.z + v.w*v.w;
    #pragma unroll
    for (int m = 16; m >= 1; m >>= 1) ss += __shfl_xor_sync(0xffffffffu, ss, m);
    __shared__ float wsum[8];
    if ((threadIdx.x & 31) == 0) wsum[threadIdx.x >> 5] = ss;
    __syncthreads();
    float tot = wsum[0]+wsum[1]+wsum[2]+wsum[3]+wsum[4]+wsum[5]+wsum[6]+wsum[7];
    float r = rsqrtf(tot * (1.0f/Dd) + EPSf);
    float4 wv = ((const float4*)w)[threadIdx.x];
    float4 o;
    o.x = v.x*r*wv.x; o.y = v.y*r*wv.y; o.z = v.z*r*wv.z; o.w = v.w*r*wv.w;
    ((float4*)(out + (size_t)row * Dd))[threadIdx.x] = o;
}

// ---------------------------------------------------------------------------
// TF32 tensor-core GEMM: C[M,N] = A[M,K] @ B[K,N] (+addsrc)
// BM=128 BN=128 BK=16, 256 threads (8 warps, 2x4), warp tile 64x32,
// mma.sync.m16n8k8.tf32, double-buffered static smem (34.3KB -> 2 CTAs/SM).
// Smem holds FRAGMENT-PERMUTED tiles: each A fragment is one LDS.128, each B
// fragment one LDS.64 per lane; permutation applied at STS time (with tf32 cvt).
// ---------------------------------------------------------------------------
#define GBM 128
#define GBN 128
#define GBK 16
#define A_BLK_STRIDE 132            // 128 + 4 pad floats per (ks,mt) fragment block
#define B_BLK_STRIDE 68             // 64 + 4 pad floats per (ks,nt) fragment block
#define A_STAGE_FLTS (16*A_BLK_STRIDE)   // 2112
#define B_STAGE_FLTS (32*B_BLK_STRIDE)   // 2176

__device__ __forceinline__ unsigned f2tf32(float f) {
    unsigned r;
    asm("cvt.rna.tf32.f32 %0, %1;" : "=r"(r) : "f"(f));
    return r;
}
__device__ __forceinline__ float f2tf32f(float f) { return __uint_as_float(f2tf32(f)); }

__device__ __forceinline__ void mma_tf32(float& c0, float& c1, float& c2, float& c3,
                                         unsigned a0, unsigned a1, unsigned a2, unsigned a3,
                                         unsigned b0, unsigned b1) {
    asm volatile(
        "mma.sync.aligned.m16n8k8.row.col.f32.tf32.tf32.f32 "
        "{%0,%1,%2,%3}, {%4,%5,%6,%7}, {%8,%9}, {%0,%1,%2,%3};"
        : "+f"(c0), "+f"(c1), "+f"(c2), "+f"(c3)
        : "r"(a0), "r"(a1), "r"(a2), "r"(a3), "r"(b0), "r"(b1));
}

__device__ __forceinline__ void mma_gemm_body(
    const float* __restrict__ A, const float* __restrict__ B,
    const float* __restrict__ addsrc, float* __restrict__ C,
    int N, int Kd, int bm, int bn) {
    __shared__ float As[2][A_STAGE_FLTS];
    __shared__ float Bs[2][B_STAGE_FLTS];

    int tid = threadIdx.x;
    int lane = tid & 31;
    int w    = tid >> 5;
    int lq = lane >> 2;         // 0..7
    int lr = lane & 3;          // 0..3
    int wm = w >> 2;            // 0..1 -> M offset wm*64
    int wn = w & 3;             // 0..3 -> N offset wn*32

    // ---- A staging decomposition: tid = [mt(3)|lq(3)|ks(1)|jk(1)] ----
    int a_jk = tid & 1;
    int a_ks = (tid >> 1) & 1;
    int a_lq = (tid >> 2) & 7;
    int a_mt = tid >> 5;
    const float* Ag = A + (size_t)(bm + a_mt*16 + a_lq) * Kd + a_ks*8 + a_jk*4;
    int a_sbase = (a_ks*8 + a_mt)*A_BLK_STRIDE + a_lq*16 + a_jk*2;   // + lr*4

    // ---- B staging decomposition: rows rb = tid>>4, nt = tid&15 ----
    int b_rb = tid >> 4;            // 0..15 (k row within chunk)
    int b_nt = tid & 15;
    int b_ks = b_rb >> 3;
    int b_kr = b_rb & 7;
    int b_lr = b_kr & 3;
    int b_jk = b_kr >> 2;
    const float* Bg = B + (size_t)b_rb * N + bn + b_nt*8;
    int b_sbase = (b_ks*16 + b_nt)*B_BLK_STRIDE + b_lr*2 + b_jk;     // + 8*i

    float acc[4][4][4];
    #pragma unroll
    for (int mi = 0; mi < 4; mi++)
        #pragma unroll
        for (int ni = 0; ni < 4; ni++)
            #pragma unroll
            for (int r = 0; r < 4; r++) acc[mi][ni][r] = 0.0f;

    int nch = Kd / GBK;

    float4 ar0, ar1, br0, br1;
    // prologue: load chunk 0
    ar0 = *(const float4*)(Ag);
    ar1 = *(const float4*)(Ag + 8*Kd);
    br0 = *(const float4*)(Bg);
    br1 = *(const float4*)(Bg + 4);

    // store stage 0 (fragment-permuted, tf32-converted)
    {
        float* as = As[0];
        float* bs = Bs[0];
        #pragma unroll
        for (int i = 0; i < 4; i++)
            *(float2*)(&as[a_sbase + i*4]) =
                make_float2(f2tf32f((&ar0.x)[i]), f2tf32f((&ar1.x)[i]));
        #pragma unroll
        for (int i = 0; i < 4; i++) bs[b_sbase + 8*i]      = f2tf32f((&br0.x)[i]);
        #pragma unroll
        for (int i = 0; i < 4; i++) bs[b_sbase + 8*(i+4)]  = f2tf32f((&br1.x)[i]);
    }
    __syncthreads();

    for (int ch = 0; ch < nch; ch++) {
        int s = ch & 1;
        if (ch + 1 < nch) {
            const float* Agn = Ag + (ch + 1) * GBK;
            const float* Bgn = Bg + (size_t)(ch + 1) * GBK * N;
            ar0 = *(const float4*)(Agn);
            ar1 = *(const float4*)(Agn + 8*Kd);
            br0 = *(const float4*)(Bgn);
            br1 = *(const float4*)(Bgn + 4);
        }

        #pragma unroll
        for (int ksi = 0; ksi < 2; ksi++) {
            float4 afv[4];
            #pragma unroll
            for (int mi = 0; mi < 4; mi++)
                afv[mi] = *(const float4*)(&As[s][(ksi*8 + wm*4 + mi)*A_BLK_STRIDE + lane*4]);
            float2 bfv[4];
            #pragma unroll
            for (int ni = 0; ni < 4; ni++)
                bfv[ni] = *(const float2*)(&Bs[s][(ksi*16 + wn*4 + ni)*B_BLK_STRIDE + lane*2]);
            #pragma unroll
            for (int mi = 0; mi < 4; mi++)
                #pragma unroll
                for (int ni = 0; ni < 4; ni++)
                    mma_tf32(acc[mi][ni][0], acc[mi][ni][1], acc[mi][ni][2], acc[mi][ni][3],
                             __float_as_uint(afv[mi].x), __float_as_uint(afv[mi].y),
                             __float_as_uint(afv[mi].z), __float_as_uint(afv[mi].w),
                             __float_as_uint(bfv[ni].x), __float_as_uint(bfv[ni].y));
        }

        if (ch + 1 < nch) {
            float* as = As[s^1];
            float* bs = Bs[s^1];
            #pragma unroll
            for (int i = 0; i < 4; i++)
                *(float2*)(&as[a_sbase + i*4]) =
                    make_float2(f2tf32f((&ar0.x)[i]), f2tf32f((&ar1.x)[i]));
            #pragma unroll
            for (int i = 0; i < 4; i++) bs[b_sbase + 8*i]     = f2tf32f((&br0.x)[i]);
            #pragma unroll
            for (int i = 0; i < 4; i++) bs[b_sbase + 8*(i+4)] = f2tf32f((&br1.x)[i]);
            __syncthreads();
        }
    }

    // epilogue
    #pragma unroll
    for (int mi = 0; mi < 4; mi++) {
        int r0 = bm + wm*64 + mi*16 + lq;
        #pragma unroll
        for (int ni = 0; ni < 4; ni++) {
            int col = bn + wn*32 + ni*8 + 2*lr;
            float2 v0 = make_float2(acc[mi][ni][0], acc[mi][ni][1]);
            float2 v1 = make_float2(acc[mi][ni][2], acc[mi][ni][3]);
            if (addsrc) {
                float2 s0 = *(const float2*)(addsrc + (size_t)r0 * N + col);
                float2 s1 = *(const float2*)(addsrc + (size_t)(r0+8) * N + col);
                v0.x += s0.x; v0.y += s0.y; v1.x += s1.x; v1.y += s1.y;
            }
            *(float2*)(C + (size_t)r0 * N + col) = v0;
            *(float2*)(C + (size_t)(r0+8) * N + col) = v1;
        }
    }
}

__global__ __launch_bounds__(256, 2) void mma_gemm_kernel(
    const float* __restrict__ A, const float* __restrict__ B,
    const float* __restrict__ addsrc, float* __restrict__ C,
    int N, int Kd) {
    mma_gemm_body(A, B, addsrc, C, N, Kd, blockIdx.y * GBM, blockIdx.x * GBN);
}

// batched QKV: blockIdx.z selects weight/output
__global__ __launch_bounds__(256, 2) void mma_gemm_qkv_kernel(
    const float* __restrict__ A,
    const float* __restrict__ B0, const float* __restrict__ B1, const float* __restrict__ B2,
    float* __restrict__ C0, float* __restrict__ C1, float* __restrict__ C2,
    int N, int Kd) {
    const float* B = (blockIdx.z == 0) ? B0 : ((blockIdx.z == 1) ? B1 : B2);
    float*       C = (blockIdx.z == 0) ? C0 : ((blockIdx.z == 1) ? C1 : C2);
    mma_gemm_body(A, B, nullptr, C, N, Kd, blockIdx.y * GBM, blockIdx.x * GBN);
}

// ---------------------------------------------------------------------------
// Fused causal depthwise conv1d (K=4) + SiLU + optional per-head L2 norm.
// One block per (b,t) row of 1024 channels; 256 threads, 4 channels each.
// ---------------------------------------------------------------------------
__global__ void conv_fused_kernel(const float* __restrict__ xin, const float* __restrict__ w,
                                  float* __restrict__ out, float scale, int do_l2) {
    int row = blockIdx.x;            // b*T + t
    int t = row & (Tt - 1);
    int c4 = threadIdx.x * 4;
    size_t base = (size_t)row * Dd + c4;

    float4 x0 = *(const float4*)(xin + base);
    float4 x1 = (t >= 1) ? *(const float4*)(xin + base - Dd)   : make_float4(0,0,0,0);
    float4 x2 = (t >= 2) ? *(const float4*)(xin + base - 2*Dd) : make_float4(0,0,0,0);
    float4 x3 = (t >= 3) ? *(const float4*)(xin + base - 3*Dd) : make_float4(0,0,0,0);

    float y[4];
    #pragma unroll
    for (int j = 0; j < 4; j++) {
        float4 w4 = ((const float4*)w)[c4 + j];
        float xc0 = (&x0.x)[j], xc1 = (&x1.x)[j], xc2 = (&x2.x)[j], xc3 = (&x3.x)[j];
        float a = xc0*w4.w + xc1*w4.z + xc2*w4.y + xc3*w4.x;
        y[j] = a / (1.0f + expf(-a));               // silu
    }

    if (do_l2) {
        float ss = y[0]*y[0] + y[1]*y[1] + y[2]*y[2] + y[3]*y[3];
        #pragma unroll
        for (int m = 8; m >= 1; m >>= 1) ss += __shfl_xor_sync(0xffffffffu, ss, m);
        float r = rsqrtf(ss + EPSf) * scale;
        #pragma unroll
        for (int j = 0; j < 4; j++) y[j] *= r;
    }
    *(float4*)(out + base) = make_float4(y[0], y[1], y[2], y[3]);
}

// ---------------------------------------------------------------------------
// Per-(b,t,h) RMSNorm over DV=64 with weight. In place.
// ---------------------------------------------------------------------------
__global__ void o_rmsnorm_kernel(float* __restrict__ o, const float* __restrict__ w) {
    int gidx = blockIdx.x * 8 + (threadIdx.x >> 5);
    int lane = threadIdx.x & 31;
    size_t base = (size_t)gidx * 64;
    float a = o[base + lane], b = o[base + 32 + lane];
    float ss = a*a + b*b;
    #pragma unroll
    for (int m = 16; m >= 1; m >>= 1) ss += __shfl_xor_sync(0xffffffffu, ss, m);
    float r = rsqrtf(ss * (1.0f/64.0f) + EPSf);
    o[base + lane]      = a * r * w[lane];
    o[base + 32 + lane] = b * r * w[lane + 32];
}

// ---------------------------------------------------------------------------
// beta / g projections
// ---------------------------------------------------------------------------
__global__ void betag_kernel(const float* __restrict__ h,
                             const float* __restrict__ Wb, const float* __restrict__ Wa,
                             const float* __restrict__ dt_bias, const float* __restrict__ A_log,
                             float* __restrict__ beta, float* __restrict__ g) {
    int row = blockIdx.x;
    __shared__ float hs[Dd];
    ((float4*)hs)[threadIdx.x] = ((const float4*)(h + (size_t)row * Dd))[threadIdx.x];
    __syncthreads();
    int hh = threadIdx.x >> 4;
    int l  = threadIdx.x & 15;
    float sb = 0.0f, sa = 0.0f;
    #pragma unroll 8
    for (int j = 0; j < 64; j++) {
        int d = l + 16*j;
        float hv = hs[d];
        sb += hv * Wb[d*Hh + hh];
        sa += hv * Wa[d*Hh + hh];
    }
    #pragma unroll
    for (int m = 8; m >= 1; m >>= 1) {
        sb += __shfl_xor_sync(0xffffffffu, sb, m);
        sa += __shfl_xor_sync(0xffffffffu, sa, m);
    }
    if (l == 0) {
        beta[row*Hh + hh] = 2.0f / (1.0f + expf(-sb));
        float xg = sa + dt_bias[hh];
        float sp = (xg > 15.0f) ? xg : log1pf(expf(xg));
        g[row*Hh + hh] = -expf(A_log[hh]) * sp;
    }
}

// ---------------------------------------------------------------------------
// Gated delta-rule scan with register prefetch. One block per (b,h).
// ---------------------------------------------------------------------------
__device__ __forceinline__ float scan_load(const float* __restrict__ q,
                                           const float* __restrict__ k,
                                           const float* __restrict__ v,
                                           const float* __restrict__ beta,
                                           const float* __restrict__ g,
                                           int b, int h, int t, int tid) {
    size_t off = ((size_t)(b*Tt + t)) * 1024 + h * 64;
    if (tid < 64)  return k[off + tid];
    if (tid < 128) return q[off + tid - 64];
    if (tid < 192) return v[off + tid - 128];
    if (tid == 192) return beta[(size_t)(b*Tt + t)*Hh + h];
    return g[(size_t)(b*Tt + t)*Hh + h];
}

__global__ __launch_bounds__(256) void scan_kernel(
    const float* __restrict__ q, const float* __restrict__ k, const float* __restrict__ v,
    const float* __restrict__ beta, const float* __restrict__ g,
    float* __restrict__ o, float* __restrict__ state_out) {
    int h = blockIdx.x, b = blockIdx.y;
    int tid = threadIdx.x;
    int c   = tid >> 2;
    int sub = tid & 3;

    __shared__ __align__(16) float sh[2][200];

    float S[16];
    #pragma unroll
    for (int r = 0; r < 16; r++) S[r] = 0.0f;

    float rv = (tid < 194) ? scan_load(q, k, v, beta, g, b, h, 0, tid) : 0.0f;

    for (int t = 0; t < Tt; t++) {
        float* buf = sh[t & 1];
        if (tid < 194) buf[tid] = rv;
        __syncthreads();
        if (t + 1 < Tt && tid < 194)
            rv = scan_load(q, k, v, beta, g, b, h, t + 1, tid);

        float eg = expf(buf[193]);
        float bt = buf[192];

        const float4* kp4 = (const float4*)(buf + sub*16);
        const float4* qp4 = (const float4*)(buf + 64 + sub*16);
        float kr[16], qr[16];
        #pragma unroll
        for (int rr = 0; rr < 4; rr++) {
            float4 kv4 = kp4[rr];
            kr[rr*4+0] = kv4.x; kr[rr*4+1] = kv4.y; kr[rr*4+2] = kv4.z; kr[rr*4+3] = kv4.w;
            float4 qv4 = qp4[rr];
            qr[rr*4+0] = qv4.x; qr[rr*4+1] = qv4.y; qr[rr*4+2] = qv4.z; qr[rr*4+3] = qv4.w;
        }

        float kvp = 0.0f;
        #pragma unroll
        for (int r = 0; r < 16; r++) {
            S[r] *= eg;
            kvp += kr[r] * S[r];
        }
        kvp += __shfl_xor_sync(0xffffffffu, kvp, 1);
        kvp += __shfl_xor_sync(0xffffffffu, kvp, 2);

        float delta = (buf[128 + c] - kvp) * bt;

        float op = 0.0f;
        #pragma unroll
        for (int r = 0; r < 16; r++) {
            S[r] += kr[r] * delta;
            op += qr[r] * S[r];
        }
        op += __shfl_xor_sync(0xffffffffu, op, 1);
        op += __shfl_xor_sync(0xffffffffu, op, 2);
        if (sub == 0)
            o[((size_t)(b*Tt + t)*Hh + h) * DV + c] = op;
    }

    #pragma unroll
    for (int r = 0; r < 16; r++)
        state_out[((size_t)(b*Hh + h)*DK + sub*16 + r) * DV + c] = S[r];
}

// ---------------------------------------------------------------------------
// SwiGLU: act = silu(gy[:, :I]) * gy[:, I:]
// ---------------------------------------------------------------------------
__global__ void swiglu_kernel(const float* __restrict__ gy, float* __restrict__ act) {
    int idx = blockIdx.x * blockDim.x + threadIdx.x;
    int row = idx / II;
    int i   = idx - row * II;
    float gate = gy[(size_t)row * (2*II) + i];
    float y    = gy[(size_t)row * (2*II) + II + i];
    act[idx] = gate / (1.0f + expf(-gate)) * y;
}

// ---------------------------------------------------------------------------
// launch
// ---------------------------------------------------------------------------
extern "C" void kernel_launch(void* const* d_in, const int* in_sizes, int n_in,
                              void* d_out, int out_size) {
    const float* x           = (const float*)d_in[0];
    const float* attn_norm_w = (const float*)d_in[1];
    const float* Wq          = (const float*)d_in[2];
    const float* Wk          = (const float*)d_in[3];
    const float* Wv          = (const float*)d_in[4];
    const float* cq          = (const float*)d_in[5];
    const float* ck          = (const float*)d_in[6];
    const float* cv          = (const float*)d_in[7];
    const float* Wb          = (const float*)d_in[8];
    const float* Wa          = (const float*)d_in[9];
    const float* dt_bias     = (const float*)d_in[10];
    const float* A_log       = (const float*)d_in[11];
    const float* o_norm_w    = (const float*)d_in[12];
    const float* Wo          = (const float*)d_in[13];
    const float* mlp_norm_w  = (const float*)d_in[14];
    const float* Wg          = (const float*)d_in[15];
    const float* Wd          = (const float*)d_in[16];
    float* out = (float*)d_out;

    float *h, *qpre, *kpre, *vpre, *q, *k, *v, *beta, *gg, *o, *h2, *h3, *gy, *act;
    cudaGetSymbolAddress((void**)&h,    g_h);
    cudaGetSymbolAddress((void**)&qpre, g_qpre);
    cudaGetSymbolAddress((void**)&kpre, g_kpre);
    cudaGetSymbolAddress((void**)&vpre, g_vpre);
    cudaGetSymbolAddress((void**)&q,    g_q);
    cudaGetSymbolAddress((void**)&k,    g_k);
    cudaGetSymbolAddress((void**)&v,    g_v);
    cudaGetSymbolAddress((void**)&beta, g_beta);
    cudaGetSymbolAddress((void**)&gg,   g_g);
    cudaGetSymbolAddress((void**)&o,    g_o);
    cudaGetSymbolAddress((void**)&h2,   g_h2);
    cudaGetSymbolAddress((void**)&h3,   g_h3);
    cudaGetSymbolAddress((void**)&gy,   g_gy);
    cudaGetSymbolAddress((void**)&act,  g_act);

    // 1. h = rmsnorm(x)
    rmsnorm_kernel<<<ROWS, 256>>>(x, attn_norm_w, h);

    // 2. q/k/v projections — one batched launch (blockIdx.z selects weight)
    dim3 gqkv(Dd/GBN, ROWS/GBM, 3);
    mma_gemm_qkv_kernel<<<gqkv, 256>>>(h, Wq, Wk, Wv, qpre, kpre, vpre, Dd, Dd);

    // 3. conv + silu (+ fused l2norm for q,k; q also scaled by DK^-0.5)
    conv_fused_kernel<<<ROWS, 256>>>(qpre, cq, q, 0.125f, 1);
    conv_fused_kernel<<<ROWS, 256>>>(kpre, ck, k, 1.0f,   1);
    conv_fused_kernel<<<ROWS, 256>>>(vpre, cv, v, 1.0f,   0);

    // 4. beta / g
    betag_kernel<<<ROWS, 256>>>(h, Wb, Wa, dt_bias, A_log, beta, gg);

    // 5. delta-rule scan (writes o and final state)
    scan_kernel<<<dim3(Hh, Bb), 256>>>(q, k, v, beta, gg, o, out + (size_t)ROWS*Dd);

    // 6. per-head output RMSNorm
    o_rmsnorm_kernel<<<(ROWS*Hh)/8, 256>>>(o, o_norm_w);

    // 7. attn projection + residual
    dim3 g1024(Dd/GBN, ROWS/GBM);
    mma_gemm_kernel<<<g1024, 256>>>(o, Wo, x, h2, Dd, Dd);

    // 8. MLP
    rmsnorm_kernel<<<ROWS, 256>>>(h2, mlp_norm_w, h3);
    dim3 gwg((2*II)/GBN, ROWS/GBM);
    mma_gemm_kernel<<<gwg, 256>>>(h3, Wg, nullptr, gy, 2*II, Dd);
    swiglu_kernel<<<(ROWS*II)/256, 256>>>(gy, act);
    mma_gemm_kernel<<<g1024, 256>>>(act, Wd, h2, out, Dd, II);
}